// round 3
// baseline (speedup 1.0000x reference)
#include <cuda_runtime.h>
#include <cuda_bf16.h>
#include <cstdint>
#include <cfloat>

#define BS   16
#define QN   1024
#define CN   92
#define TN   128

// Transposed cost Ct[b][t][q] so the JV row scan is coalesced.
__device__ float g_Ct[BS * TN * QN];
__device__ int   g_lbl64;

// ---------------------------------------------------------------------------
__global__ void detect_label_dtype(const int* __restrict__ lab32) {
    __shared__ int ok;
    if (threadIdx.x == 0) ok = 1;
    __syncthreads();
    for (int t = threadIdx.x; t < 1024; t += blockDim.x)
        if (lab32[2 * t + 1] != 0) ok = 0;
    __syncthreads();
    if (threadIdx.x == 0) g_lbl64 = ok;
}

// ---------------------------------------------------------------------------
// Cost kernel: one WARP per query. Block = 8 warps = 8 queries.
// ---------------------------------------------------------------------------
__global__ void __launch_bounds__(256)
cost_kernel(const float* __restrict__ logits,
            const float* __restrict__ points,
            const int*   __restrict__ lab32,
            const float* __restrict__ tpoints,
            float* __restrict__ outC)
{
    const int warp = threadIdx.x >> 5, lane = threadIdx.x & 31;
    const int bq = blockIdx.x * 8 + warp;
    const int b  = bq >> 10, q = bq & 1023;

    __shared__ float slog[8][96];
    __shared__ int   slbl[TN];
    __shared__ float stx[TN], sty[TN];

    if (threadIdx.x < TN) {
        const int lidx = b * TN + threadIdx.x;
        slbl[threadIdx.x] = g_lbl64 ? lab32[2 * lidx] : lab32[lidx];
        stx[threadIdx.x]  = tpoints[lidx * 2];
        sty[threadIdx.x]  = tpoints[lidx * 2 + 1];
    }

    const float* lg = logits + (size_t)bq * CN;
    const float a  = lg[lane];
    const float bb = lg[lane + 32];
    const float c  = (lane < 28) ? lg[lane + 64] : -FLT_MAX;
    slog[warp][lane]      = a;
    slog[warp][lane + 32] = bb;
    if (lane < 28) slog[warp][lane + 64] = c;

    float mx = fmaxf(a, fmaxf(bb, c));
    #pragma unroll
    for (int o = 16; o > 0; o >>= 1) mx = fmaxf(mx, __shfl_xor_sync(0xffffffffu, mx, o));

    float e = expf(a - mx) + expf(bb - mx) + ((lane < 28) ? expf(c - mx) : 0.f);
    #pragma unroll
    for (int o = 16; o > 0; o >>= 1) e += __shfl_xor_sync(0xffffffffu, e, o);
    const float inv = 1.f / e;

    const float px = __ldg(points + bq * 2);
    const float py = __ldg(points + bq * 2 + 1);
    __syncthreads();

    #pragma unroll
    for (int c2 = 0; c2 < 4; c2++) {
        const int t = c2 * 32 + lane;
        const float prob = expf(slog[warp][slbl[t]] - mx) * inv;
        const float cost = fabsf(px - stx[t]) + fabsf(py - sty[t]) - prob;
        outC[(size_t)bq * TN + t] = cost;
        g_Ct[((size_t)b * TN + t) * QN + q] = cost;
    }
}

// ---------------------------------------------------------------------------
__device__ __forceinline__ unsigned long long dkey(double x) {
    unsigned long long u = __double_as_longlong(x);
    return (u & 0x8000000000000000ULL) ? ~u : (u ^ 0x8000000000000000ULL);
}

// ---------------------------------------------------------------------------
// Dijkstra-form JV (scipy-style): duals updated ONCE per augmentation,
// one barrier per step, 3-slot rotating argmin key (race-free reset),
// 128 threads, 8 columns/thread, SP & v in registers (SP mirrored in SMEM
// only for the exact-minVal broadcast).
// ---------------------------------------------------------------------------
__global__ void __launch_bounds__(128, 1)
lsa_kernel(float* __restrict__ outRow, float* __restrict__ outCol)
{
    const int b = blockIdx.x, tid = threadIdx.x;

    __shared__ double u_[TN];
    __shared__ double SPsh[QN];
    __shared__ int    path_[QN];
    __shared__ int    row4col_[QN];
    __shared__ int    col4row_[TN];
    __shared__ unsigned long long s_key[3];

    const float* C = g_Ct + (size_t)b * TN * QN;
    const double DINF = 1e300;

    u_[tid] = 0.0;
    col4row_[tid] = -1;
    #pragma unroll
    for (int k = 0; k < 8; k++) row4col_[tid * 8 + k] = -1;
    if (tid == 0) { s_key[0] = ~0ULL; s_key[1] = ~0ULL; s_key[2] = ~0ULL; }
    __syncthreads();

    double v[8] = {0, 0, 0, 0, 0, 0, 0, 0};
    int t = 0;  // global step counter (slot rotation)

    for (int curRow = 0; curRow < TN; ++curRow) {
        double SP[8];
        #pragma unroll
        for (int k = 0; k < 8; k++) SP[k] = DINF;
        int usedm = 0;
        int i = curRow;
        double minVal = 0.0;
        int jsink;

        while (true) {
            if (tid == 0) s_key[(t + 1) % 3] = ~0ULL;   // reset future slot
            const double h = minVal - u_[i];

            const float4* row = (const float4*)(C + (size_t)i * QN);
            const float4 c0 = __ldg(row + tid * 2);
            const float4 c1 = __ldg(row + tid * 2 + 1);
            const float cf[8] = {c0.x, c0.y, c0.z, c0.w, c1.x, c1.y, c1.z, c1.w};

            unsigned long long lkey = ~0ULL;
            #pragma unroll
            for (int k = 0; k < 8; k++) {
                if (!((usedm >> k) & 1)) {
                    const int j = tid * 8 + k;
                    const double r = (double)cf[k] + h - v[k];
                    if (r < SP[k]) { SP[k] = r; path_[j] = i; SPsh[j] = r; }
                    const unsigned long long kk =
                        (dkey(SP[k]) & ~2047ULL) | (unsigned long long)j;
                    if (kk < lkey) lkey = kk;
                }
            }
            if (lkey != ~0ULL) atomicMin(&s_key[t % 3], lkey);
            __syncthreads();                             // the ONLY per-step bar

            const int j1 = (int)(s_key[t % 3] & 2047ULL);
            minVal = SPsh[j1];                           // exact double
            const int kown = j1 - tid * 8;
            if (kown >= 0 && kown < 8) usedm |= (1 << kown);
            const int nr = row4col_[j1];
            t++;
            if (nr < 0) { jsink = j1; break; }
            i = nr;
        }

        // Dual update (once per augmentation). Reads row4col_ BEFORE augment.
        #pragma unroll
        for (int k = 0; k < 8; k++) {
            if ((usedm >> k) & 1) {
                const int j = tid * 8 + k;
                const double d = minVal - SP[k];
                v[k] -= d;
                const int rj = row4col_[j];
                if (rj >= 0) u_[rj] += d;                // distinct rows, no race
            }
        }
        if (tid == 0) u_[curRow] += minVal;
        __syncthreads();

        if (tid == 0) {                                  // augment
            int j = jsink;
            while (true) {
                const int ii = path_[j];
                row4col_[j] = ii;
                const int tmp = col4row_[ii];
                col4row_[ii] = j;
                if (ii == curRow) break;
                j = tmp;
            }
        }
        __syncthreads();
    }

    // col4row_[t] = assigned query for target t; sort by query index.
    const int a = col4row_[tid];
    int r = 0;
    #pragma unroll 8
    for (int s = 0; s < TN; ++s) r += (col4row_[s] < a);
    outRow[b * TN + r] = (float)a;
    outCol[b * TN + r] = (float)tid;
}

// ---------------------------------------------------------------------------
extern "C" void kernel_launch(void* const* d_in, const int* in_sizes, int n_in,
                              void* d_out, int out_size)
{
    const float* logits  = (const float*)d_in[0];
    const float* points  = (const float*)d_in[1];
    const int*   labels  = (const int*)  d_in[2];
    const float* tpoints = (const float*)d_in[3];

    float* out    = (float*)d_out;
    float* outC   = out;
    float* outRow = out + (size_t)BS * QN * TN;
    float* outCol = outRow + BS * TN;

    detect_label_dtype<<<1, 256>>>(labels);
    cost_kernel<<<BS * QN / 8, 256>>>(logits, points, labels, tpoints, outC);
    lsa_kernel<<<BS, 128>>>(outRow, outCol);
}

// round 4
// speedup vs baseline: 1.8041x; 1.8041x over previous
#include <cuda_runtime.h>
#include <cuda_bf16.h>
#include <cstdint>
#include <cfloat>

#define BS   16
#define QN   1024
#define CN   92
#define TN   128

// Transposed cost Ct[b][t][q] so the JV row scan is coalesced.
__device__ float g_Ct[BS * TN * QN];
__device__ int   g_lbl64;

// ---------------------------------------------------------------------------
__global__ void detect_label_dtype(const int* __restrict__ lab32) {
    __shared__ int ok;
    if (threadIdx.x == 0) ok = 1;
    __syncthreads();
    for (int t = threadIdx.x; t < 1024; t += blockDim.x)
        if (lab32[2 * t + 1] != 0) ok = 0;
    __syncthreads();
    if (threadIdx.x == 0) g_lbl64 = ok;
}

// ---------------------------------------------------------------------------
// Cost kernel: one WARP per query. Softmax probs computed once (92 expf),
// stored in smem; the per-target loop is pure gather+FMA (no expf).
// ---------------------------------------------------------------------------
__global__ void __launch_bounds__(256)
cost_kernel(const float* __restrict__ logits,
            const float* __restrict__ points,
            const int*   __restrict__ lab32,
            const float* __restrict__ tpoints,
            float* __restrict__ outC)
{
    const int warp = threadIdx.x >> 5, lane = threadIdx.x & 31;
    const int bq = blockIdx.x * 8 + warp;
    const int b  = bq >> 10, q = bq & 1023;

    __shared__ float sprob[8][96];
    __shared__ int   slbl[TN];
    __shared__ float stx[TN], sty[TN];

    if (threadIdx.x < TN) {
        const int lidx = b * TN + threadIdx.x;
        slbl[threadIdx.x] = g_lbl64 ? lab32[2 * lidx] : lab32[lidx];
        stx[threadIdx.x]  = tpoints[lidx * 2];
        sty[threadIdx.x]  = tpoints[lidx * 2 + 1];
    }

    const float* lg = logits + (size_t)bq * CN;
    const float a  = lg[lane];
    const float bb = lg[lane + 32];
    const float c  = (lane < 28) ? lg[lane + 64] : -FLT_MAX;

    float mx = fmaxf(a, fmaxf(bb, c));
    #pragma unroll
    for (int o = 16; o > 0; o >>= 1) mx = fmaxf(mx, __shfl_xor_sync(0xffffffffu, mx, o));

    const float ea = expf(a - mx);
    const float eb = expf(bb - mx);
    const float ec = (lane < 28) ? expf(c - mx) : 0.f;
    float e = ea + eb + ec;
    #pragma unroll
    for (int o = 16; o > 0; o >>= 1) e += __shfl_xor_sync(0xffffffffu, e, o);
    const float inv = 1.f / e;

    sprob[warp][lane]      = ea * inv;
    sprob[warp][lane + 32] = eb * inv;
    if (lane < 28) sprob[warp][lane + 64] = ec * inv;

    const float px = __ldg(points + bq * 2);
    const float py = __ldg(points + bq * 2 + 1);
    __syncthreads();

    #pragma unroll
    for (int c2 = 0; c2 < 4; c2++) {
        const int t = c2 * 32 + lane;
        const float cost = fabsf(px - stx[t]) + fabsf(py - sty[t])
                         - sprob[warp][slbl[t]];
        outC[(size_t)bq * TN + t] = cost;
        g_Ct[((size_t)b * TN + t) * QN + q] = cost;
    }
}

// ---------------------------------------------------------------------------
__device__ __forceinline__ unsigned long long dkey(double x) {
    unsigned long long u = __double_as_longlong(x);
    return (u & 0x8000000000000000ULL) ? ~u : (u ^ 0x8000000000000000ULL);
}

// ---------------------------------------------------------------------------
// Dijkstra-form JV (scipy-style), 256 threads x 4 cols/thread.
// One barrier per step; duals updated once per augmentation.
// Argmin: 5-level warp shuffle reduce on packed u64 key, then ONE lane-0
// atomicMin per warp into a 3-slot rotating key (race-free reset).
// Exact double minVal recovered via SPsh[j1].
// ---------------------------------------------------------------------------
__global__ void __launch_bounds__(256, 1)
lsa_kernel(float* __restrict__ outRow, float* __restrict__ outCol)
{
    const int b = blockIdx.x, tid = threadIdx.x;
    const int lane = tid & 31;

    __shared__ double u_[TN];
    __shared__ double SPsh[QN];
    __shared__ int    path_[QN];
    __shared__ int    row4col_[QN];
    __shared__ int    col4row_[TN];
    __shared__ unsigned long long s_key[3];

    const float* C = g_Ct + (size_t)b * TN * QN;
    const double DINF = 1e300;

    if (tid < TN) { u_[tid] = 0.0; col4row_[tid] = -1; }
    #pragma unroll
    for (int k = 0; k < 4; k++) row4col_[tid * 4 + k] = -1;
    if (tid == 0) { s_key[0] = ~0ULL; s_key[1] = ~0ULL; s_key[2] = ~0ULL; }
    __syncthreads();

    double v[4] = {0, 0, 0, 0};
    int t = 0;  // global step counter (slot rotation)

    for (int curRow = 0; curRow < TN; ++curRow) {
        double SP[4] = {DINF, DINF, DINF, DINF};
        int usedm = 0;
        int i = curRow;
        double minVal = 0.0;
        int jsink;

        while (true) {
            // issue row load FIRST (longest latency, independent of the rest)
            const float4 cc = __ldg((const float4*)(C + (size_t)i * QN) + tid);
            if (tid == 0) s_key[(t + 1) % 3] = ~0ULL;   // reset future slot
            const double h = minVal - u_[i];
            const float cf[4] = {cc.x, cc.y, cc.z, cc.w};

            unsigned long long lkey = ~0ULL;
            #pragma unroll
            for (int k = 0; k < 4; k++) {
                if (!((usedm >> k) & 1)) {
                    const int j = tid * 4 + k;
                    const double r = (double)cf[k] + h - v[k];
                    if (r < SP[k]) { SP[k] = r; path_[j] = i; SPsh[j] = r; }
                    const unsigned long long kk =
                        (dkey(SP[k]) & ~2047ULL) | (unsigned long long)j;
                    if (kk < lkey) lkey = kk;
                }
            }
            // warp min-reduce, one atomic per warp
            #pragma unroll
            for (int o = 16; o > 0; o >>= 1) {
                const unsigned long long ok =
                    __shfl_xor_sync(0xffffffffu, lkey, o);
                if (ok < lkey) lkey = ok;
            }
            if (lane == 0 && lkey != ~0ULL) atomicMin(&s_key[t % 3], lkey);
            __syncthreads();                             // the ONLY per-step bar

            const int j1 = (int)(s_key[t % 3] & 2047ULL);
            const int nr = row4col_[j1];
            minVal = SPsh[j1];                           // exact double
            const int kown = j1 - tid * 4;
            if (kown >= 0 && kown < 4) usedm |= (1 << kown);
            t++;
            if (nr < 0) { jsink = j1; break; }
            i = nr;
        }

        // Dual update (once per augmentation). Reads row4col_ BEFORE augment.
        #pragma unroll
        for (int k = 0; k < 4; k++) {
            if ((usedm >> k) & 1) {
                const int j = tid * 4 + k;
                const double d = minVal - SP[k];
                v[k] -= d;
                const int rj = row4col_[j];
                if (rj >= 0) u_[rj] += d;                // distinct rows, no race
            }
        }
        if (tid == 0) u_[curRow] += minVal;
        __syncthreads();

        if (tid == 0) {                                  // augment
            int j = jsink;
            while (true) {
                const int ii = path_[j];
                row4col_[j] = ii;
                const int tmp = col4row_[ii];
                col4row_[ii] = j;
                if (ii == curRow) break;
                j = tmp;
            }
        }
        __syncthreads();
    }

    // col4row_[t] = assigned query for target t; sort by query index.
    if (tid < TN) {
        const int a = col4row_[tid];
        int r = 0;
        #pragma unroll 8
        for (int s = 0; s < TN; ++s) r += (col4row_[s] < a);
        outRow[b * TN + r] = (float)a;
        outCol[b * TN + r] = (float)tid;
    }
}

// ---------------------------------------------------------------------------
extern "C" void kernel_launch(void* const* d_in, const int* in_sizes, int n_in,
                              void* d_out, int out_size)
{
    const float* logits  = (const float*)d_in[0];
    const float* points  = (const float*)d_in[1];
    const int*   labels  = (const int*)  d_in[2];
    const float* tpoints = (const float*)d_in[3];

    float* out    = (float*)d_out;
    float* outC   = out;
    float* outRow = out + (size_t)BS * QN * TN;
    float* outCol = outRow + BS * TN;

    detect_label_dtype<<<1, 256>>>(labels);
    cost_kernel<<<BS * QN / 8, 256>>>(logits, points, labels, tpoints, outC);
    lsa_kernel<<<BS, 256>>>(outRow, outCol);
}

// round 5
// speedup vs baseline: 3.6608x; 2.0292x over previous
#include <cuda_runtime.h>
#include <cuda_bf16.h>
#include <cstdint>
#include <cfloat>

#define BS   16
#define QN   1024
#define CN   92
#define TN   128

// Transposed cost Ct[b][t][q] so the JV row scan is coalesced.
__device__ float g_Ct[BS * TN * QN];

// ---------------------------------------------------------------------------
// Cost kernel: one WARP per query; softmax probs computed once per query.
// Label-dtype detection (int64 vs int32 layout) done inline per block using
// only 32-bit words 1..255 of the label buffer (in-bounds for both layouts;
// odd words all-zero => int64 little-endian layout).
// ---------------------------------------------------------------------------
__global__ void __launch_bounds__(256)
cost_kernel(const float* __restrict__ logits,
            const float* __restrict__ points,
            const int*   __restrict__ lab32,
            const float* __restrict__ tpoints,
            float* __restrict__ outC)
{
    const int warp = threadIdx.x >> 5, lane = threadIdx.x & 31;
    const int bq = blockIdx.x * 8 + warp;
    const int b  = bq >> 10, q = bq & 1023;

    __shared__ float sprob[8][96];
    __shared__ int   slbl[TN];
    __shared__ float stx[TN], sty[TN];
    __shared__ int   s_lbl64;

    if (threadIdx.x == 0) s_lbl64 = 1;
    __syncthreads();
    if (threadIdx.x < TN) {
        if (lab32[2 * threadIdx.x + 1] != 0) s_lbl64 = 0;
    }
    __syncthreads();
    const int lbl64 = s_lbl64;

    if (threadIdx.x < TN) {
        const int lidx = b * TN + threadIdx.x;
        slbl[threadIdx.x] = lbl64 ? lab32[2 * lidx] : lab32[lidx];
        stx[threadIdx.x]  = tpoints[lidx * 2];
        sty[threadIdx.x]  = tpoints[lidx * 2 + 1];
    }

    const float* lg = logits + (size_t)bq * CN;
    const float a  = lg[lane];
    const float bb = lg[lane + 32];
    const float c  = (lane < 28) ? lg[lane + 64] : -FLT_MAX;

    float mx = fmaxf(a, fmaxf(bb, c));
    #pragma unroll
    for (int o = 16; o > 0; o >>= 1) mx = fmaxf(mx, __shfl_xor_sync(0xffffffffu, mx, o));

    const float ea = expf(a - mx);
    const float eb = expf(bb - mx);
    const float ec = (lane < 28) ? expf(c - mx) : 0.f;
    float e = ea + eb + ec;
    #pragma unroll
    for (int o = 16; o > 0; o >>= 1) e += __shfl_xor_sync(0xffffffffu, e, o);
    const float inv = 1.f / e;

    sprob[warp][lane]      = ea * inv;
    sprob[warp][lane + 32] = eb * inv;
    if (lane < 28) sprob[warp][lane + 64] = ec * inv;

    const float px = __ldg(points + bq * 2);
    const float py = __ldg(points + bq * 2 + 1);
    __syncthreads();

    #pragma unroll
    for (int c2 = 0; c2 < 4; c2++) {
        const int t = c2 * 32 + lane;
        const float cost = fabsf(px - stx[t]) + fabsf(py - sty[t])
                         - sprob[warp][slbl[t]];
        outC[(size_t)bq * TN + t] = cost;     // coalesced only
    }
}

// ---------------------------------------------------------------------------
// Tiled transpose: Cb[b,q,t] -> Ct[b,t,q]. Fully coalesced both ways.
// ---------------------------------------------------------------------------
__global__ void __launch_bounds__(1024)
transpose_kernel(const float* __restrict__ outC)
{
    __shared__ float tile[32][33];
    const int b  = blockIdx.z;
    const int q0 = blockIdx.x * 32;
    const int t0 = blockIdx.y * 32;
    const int tx = threadIdx.x & 31, ty = threadIdx.x >> 5;

    tile[ty][tx] = outC[((size_t)(b << 10) + q0 + ty) * TN + t0 + tx];
    __syncthreads();
    g_Ct[((size_t)b * TN + t0 + ty) * QN + q0 + tx] = tile[tx][ty];
}

// ---------------------------------------------------------------------------
__device__ __forceinline__ unsigned long long dkey(double x) {
    unsigned long long u = __double_as_longlong(x);
    return (u & 0x8000000000000000ULL) ? ~u : (u ^ 0x8000000000000000ULL);
}

// ---------------------------------------------------------------------------
// JV with row-reduction init + Dijkstra augmentation (scipy-compatible optimum).
// Phase 0: u[i] = row min (parallel, barrier-free atomics per row slot).
// Phase 1: greedy-assign rows to their argmin column (parallel atomicCAS).
// Phase 2: Dijkstra shortest augmenting path for the ~8 unassigned rows.
// ---------------------------------------------------------------------------
__global__ void __launch_bounds__(256, 1)
lsa_kernel(float* __restrict__ outRow, float* __restrict__ outCol)
{
    const int b = blockIdx.x, tid = threadIdx.x;
    const int lane = tid & 31;

    __shared__ double u_[TN];
    __shared__ double SPsh[QN];
    __shared__ int    path_[QN];
    __shared__ int    row4col_[QN];
    __shared__ int    col4row_[TN];
    __shared__ unsigned long long s_key[3];
    __shared__ unsigned long long s_rowkey[TN];

    const float* C = g_Ct + (size_t)b * TN * QN;
    const double DINF = 1e300;

    #pragma unroll
    for (int k = 0; k < 4; k++) row4col_[tid * 4 + k] = -1;
    if (tid < TN) s_rowkey[tid] = ~0ULL;
    if (tid == 0) { s_key[0] = ~0ULL; s_key[1] = ~0ULL; s_key[2] = ~0ULL; }
    __syncthreads();

    // ---- Phase 0: per-row minima (no per-row barriers) ----
    for (int r = 0; r < TN; ++r) {
        const float4 cc = __ldg((const float4*)(C + (size_t)r * QN) + tid);
        const float cf[4] = {cc.x, cc.y, cc.z, cc.w};
        unsigned long long lkey = ~0ULL;
        #pragma unroll
        for (int k = 0; k < 4; k++) {
            const unsigned long long kk =
                (dkey((double)cf[k]) & ~2047ULL) | (unsigned long long)(tid * 4 + k);
            if (kk < lkey) lkey = kk;
        }
        #pragma unroll
        for (int o = 16; o > 0; o >>= 1) {
            const unsigned long long ok = __shfl_xor_sync(0xffffffffu, lkey, o);
            if (ok < lkey) lkey = ok;
        }
        if (lane == 0) atomicMin(&s_rowkey[r], lkey);
    }
    __syncthreads();

    // ---- Phase 1: duals + greedy assignment ----
    if (tid < TN) {
        const int js = (int)(s_rowkey[tid] & 2047ULL);
        u_[tid] = (double)__ldg(C + (size_t)tid * QN + js);
        const int old = atomicCAS(&row4col_[js], -1, tid);
        col4row_[tid] = (old == -1) ? js : -1;
    }
    __syncthreads();

    // ---- Phase 2: augment unassigned rows ----
    double v[4] = {0, 0, 0, 0};
    int t = 0;

    for (int curRow = 0; curRow < TN; ++curRow) {
        if (col4row_[curRow] >= 0) continue;

        double SP[4] = {DINF, DINF, DINF, DINF};
        int usedm = 0;
        int i = curRow;
        double minVal = 0.0;
        int jsink;

        while (true) {
            const float4 cc = __ldg((const float4*)(C + (size_t)i * QN) + tid);
            if (tid == 0) s_key[(t + 1) % 3] = ~0ULL;
            const double h = minVal - u_[i];
            const float cf[4] = {cc.x, cc.y, cc.z, cc.w};

            unsigned long long lkey = ~0ULL;
            #pragma unroll
            for (int k = 0; k < 4; k++) {
                if (!((usedm >> k) & 1)) {
                    const int j = tid * 4 + k;
                    const double r = (double)cf[k] + h - v[k];
                    if (r < SP[k]) { SP[k] = r; path_[j] = i; SPsh[j] = r; }
                    const unsigned long long kk =
                        (dkey(SP[k]) & ~2047ULL) | (unsigned long long)j;
                    if (kk < lkey) lkey = kk;
                }
            }
            #pragma unroll
            for (int o = 16; o > 0; o >>= 1) {
                const unsigned long long ok = __shfl_xor_sync(0xffffffffu, lkey, o);
                if (ok < lkey) lkey = ok;
            }
            if (lane == 0 && lkey != ~0ULL) atomicMin(&s_key[t % 3], lkey);
            __syncthreads();                       // the ONLY per-step barrier

            const int j1 = (int)(s_key[t % 3] & 2047ULL);
            const int nr = row4col_[j1];
            minVal = SPsh[j1];                     // exact double
            const int kown = j1 - tid * 4;
            if (kown >= 0 && kown < 4) usedm |= (1 << kown);
            t++;
            if (nr < 0) { jsink = j1; break; }
            i = nr;
        }

        // dual update once per augmentation (reads row4col_ BEFORE augment)
        #pragma unroll
        for (int k = 0; k < 4; k++) {
            if ((usedm >> k) & 1) {
                const int j = tid * 4 + k;
                const double d = minVal - SP[k];
                v[k] -= d;
                const int rj = row4col_[j];
                if (rj >= 0) u_[rj] += d;
            }
        }
        if (tid == 0) u_[curRow] += minVal;
        __syncthreads();

        if (tid == 0) {                            // augment
            int j = jsink;
            while (true) {
                const int ii = path_[j];
                row4col_[j] = ii;
                const int tmp = col4row_[ii];
                col4row_[ii] = j;
                if (ii == curRow) break;
                j = tmp;
            }
        }
        __syncthreads();
    }

    // col4row_[t] = assigned query for target t; emit sorted by query index.
    if (tid < TN) {
        const int a = col4row_[tid];
        int r = 0;
        #pragma unroll 8
        for (int s = 0; s < TN; ++s) r += (col4row_[s] < a);
        outRow[b * TN + r] = (float)a;
        outCol[b * TN + r] = (float)tid;
    }
}

// ---------------------------------------------------------------------------
extern "C" void kernel_launch(void* const* d_in, const int* in_sizes, int n_in,
                              void* d_out, int out_size)
{
    const float* logits  = (const float*)d_in[0];
    const float* points  = (const float*)d_in[1];
    const int*   labels  = (const int*)  d_in[2];
    const float* tpoints = (const float*)d_in[3];

    float* out    = (float*)d_out;
    float* outC   = out;
    float* outRow = out + (size_t)BS * QN * TN;
    float* outCol = outRow + BS * TN;

    cost_kernel<<<BS * QN / 8, 256>>>(logits, points, labels, tpoints, outC);
    dim3 tg(QN / 32, TN / 32, BS);
    transpose_kernel<<<tg, 1024>>>(outC);
    lsa_kernel<<<BS, 256>>>(outRow, outCol);
}

// round 6
// speedup vs baseline: 6.7752x; 1.8508x over previous
#include <cuda_runtime.h>
#include <cuda_bf16.h>
#include <cstdint>
#include <cfloat>

#define BS   16
#define QN   1024
#define CN   92
#define TN   128

// Transposed cost Ct[b][t][q] so the JV row scan is coalesced.
__device__ float g_Ct[BS * TN * QN];
// Per-(b,t) packed row-min key: fkey(fp32 cost)<<11 | argmin column.
__device__ unsigned long long g_rowkey[BS * TN];

// order-preserving fp32 -> u32 key and inverse
__device__ __forceinline__ unsigned int fkey(float x) {
    unsigned int u = __float_as_uint(x);
    return (u & 0x80000000u) ? ~u : (u ^ 0x80000000u);
}
__device__ __forceinline__ float fkey_inv(unsigned int k) {
    unsigned int u = (k & 0x80000000u) ? (k ^ 0x80000000u) : ~k;
    return __uint_as_float(u);
}
__device__ __forceinline__ unsigned long long dkey(double x) {
    unsigned long long u = __double_as_longlong(x);
    return (u & 0x8000000000000000ULL) ? ~u : (u ^ 0x8000000000000000ULL);
}

// ---------------------------------------------------------------------------
// Cost kernel: one WARP per query; softmax probs computed once per query.
// Block 0 also resets g_rowkey (runs before the transpose kernel).
// ---------------------------------------------------------------------------
__global__ void __launch_bounds__(256)
cost_kernel(const float* __restrict__ logits,
            const float* __restrict__ points,
            const int*   __restrict__ lab32,
            const float* __restrict__ tpoints,
            float* __restrict__ outC)
{
    const int warp = threadIdx.x >> 5, lane = threadIdx.x & 31;
    const int bq = blockIdx.x * 8 + warp;
    const int b  = bq >> 10, q = bq & 1023;

    if (blockIdx.x == 0) {
        #pragma unroll
        for (int k = 0; k < (BS * TN) / 256; k++)
            g_rowkey[k * 256 + threadIdx.x] = ~0ULL;
    }

    __shared__ float sprob[8][96];
    __shared__ int   slbl[TN];
    __shared__ float stx[TN], sty[TN];
    __shared__ int   s_lbl64;

    if (threadIdx.x == 0) s_lbl64 = 1;
    __syncthreads();
    if (threadIdx.x < TN) {
        if (lab32[2 * threadIdx.x + 1] != 0) s_lbl64 = 0;
    }
    __syncthreads();
    const int lbl64 = s_lbl64;

    if (threadIdx.x < TN) {
        const int lidx = b * TN + threadIdx.x;
        slbl[threadIdx.x] = lbl64 ? lab32[2 * lidx] : lab32[lidx];
        stx[threadIdx.x]  = tpoints[lidx * 2];
        sty[threadIdx.x]  = tpoints[lidx * 2 + 1];
    }

    const float* lg = logits + (size_t)bq * CN;
    const float a  = lg[lane];
    const float bb = lg[lane + 32];
    const float c  = (lane < 28) ? lg[lane + 64] : -FLT_MAX;

    float mx = fmaxf(a, fmaxf(bb, c));
    #pragma unroll
    for (int o = 16; o > 0; o >>= 1) mx = fmaxf(mx, __shfl_xor_sync(0xffffffffu, mx, o));

    const float ea = expf(a - mx);
    const float eb = expf(bb - mx);
    const float ec = (lane < 28) ? expf(c - mx) : 0.f;
    float e = ea + eb + ec;
    #pragma unroll
    for (int o = 16; o > 0; o >>= 1) e += __shfl_xor_sync(0xffffffffu, e, o);
    const float inv = 1.f / e;

    sprob[warp][lane]      = ea * inv;
    sprob[warp][lane + 32] = eb * inv;
    if (lane < 28) sprob[warp][lane + 64] = ec * inv;

    const float px = __ldg(points + bq * 2);
    const float py = __ldg(points + bq * 2 + 1);
    __syncthreads();

    #pragma unroll
    for (int c2 = 0; c2 < 4; c2++) {
        const int t = c2 * 32 + lane;
        const float cost = fabsf(px - stx[t]) + fabsf(py - sty[t])
                         - sprob[warp][slbl[t]];
        outC[(size_t)bq * TN + t] = cost;     // coalesced only
    }
}

// ---------------------------------------------------------------------------
// Tiled transpose Cb[b,q,t] -> Ct[b,t,q], fused row-min:
// warp ty owns target t0+ty; 5-level u64 shuffle reduce over its 32 q's,
// then ONE global atomicMin per warp. Fully parallel across 2048 blocks.
// ---------------------------------------------------------------------------
__global__ void __launch_bounds__(1024)
transpose_kernel(const float* __restrict__ outC)
{
    __shared__ float tile[32][33];
    const int b  = blockIdx.z;
    const int q0 = blockIdx.x * 32;
    const int t0 = blockIdx.y * 32;
    const int tx = threadIdx.x & 31, ty = threadIdx.x >> 5;

    tile[ty][tx] = outC[((size_t)(b << 10) + q0 + ty) * TN + t0 + tx];
    __syncthreads();
    const float val = tile[tx][ty];
    g_Ct[((size_t)b * TN + t0 + ty) * QN + q0 + tx] = val;

    // row-min (over q) for target t0+ty
    unsigned long long lkey =
        ((unsigned long long)fkey(val) << 11) | (unsigned long long)(q0 + tx);
    #pragma unroll
    for (int o = 16; o > 0; o >>= 1) {
        const unsigned long long ok = __shfl_xor_sync(0xffffffffu, lkey, o);
        if (ok < lkey) lkey = ok;
    }
    if (tx == 0) atomicMin(&g_rowkey[b * TN + t0 + ty], lkey);
}

// ---------------------------------------------------------------------------
// JV: row-reduction duals from g_rowkey, greedy CAS assignment, then
// Dijkstra shortest augmenting paths for the ~8 unassigned rows.
// ---------------------------------------------------------------------------
__global__ void __launch_bounds__(256, 1)
lsa_kernel(float* __restrict__ outRow, float* __restrict__ outCol)
{
    const int b = blockIdx.x, tid = threadIdx.x;
    const int lane = tid & 31;

    __shared__ double u_[TN];
    __shared__ double SPsh[QN];
    __shared__ int    path_[QN];
    __shared__ int    row4col_[QN];
    __shared__ int    col4row_[TN];
    __shared__ unsigned long long s_key[3];

    const float* C = g_Ct + (size_t)b * TN * QN;
    const double DINF = 1e300;

    #pragma unroll
    for (int k = 0; k < 4; k++) row4col_[tid * 4 + k] = -1;
    if (tid == 0) { s_key[0] = ~0ULL; s_key[1] = ~0ULL; s_key[2] = ~0ULL; }
    __syncthreads();

    // ---- duals + greedy assignment from precomputed row-min keys ----
    if (tid < TN) {
        const unsigned long long key = g_rowkey[b * TN + tid];
        const int js = (int)(key & 2047ULL);
        u_[tid] = (double)fkey_inv((unsigned int)(key >> 11));
        const int old = atomicCAS(&row4col_[js], -1, tid);
        col4row_[tid] = (old == -1) ? js : -1;
    }
    __syncthreads();

    // ---- Dijkstra augmentation for unassigned rows ----
    double v[4] = {0, 0, 0, 0};
    int t = 0;

    for (int curRow = 0; curRow < TN; ++curRow) {
        if (col4row_[curRow] >= 0) continue;

        double SP[4] = {DINF, DINF, DINF, DINF};
        int usedm = 0;
        int i = curRow;
        double minVal = 0.0;
        int jsink;

        while (true) {
            const float4 cc = __ldg((const float4*)(C + (size_t)i * QN) + tid);
            if (tid == 0) s_key[(t + 1) % 3] = ~0ULL;
            const double h = minVal - u_[i];
            const float cf[4] = {cc.x, cc.y, cc.z, cc.w};

            unsigned long long lkey = ~0ULL;
            #pragma unroll
            for (int k = 0; k < 4; k++) {
                if (!((usedm >> k) & 1)) {
                    const int j = tid * 4 + k;
                    const double r = (double)cf[k] + h - v[k];
                    if (r < SP[k]) { SP[k] = r; path_[j] = i; SPsh[j] = r; }
                    const unsigned long long kk =
                        (dkey(SP[k]) & ~2047ULL) | (unsigned long long)j;
                    if (kk < lkey) lkey = kk;
                }
            }
            #pragma unroll
            for (int o = 16; o > 0; o >>= 1) {
                const unsigned long long ok = __shfl_xor_sync(0xffffffffu, lkey, o);
                if (ok < lkey) lkey = ok;
            }
            if (lane == 0 && lkey != ~0ULL) atomicMin(&s_key[t % 3], lkey);
            __syncthreads();                       // the ONLY per-step barrier

            const int j1 = (int)(s_key[t % 3] & 2047ULL);
            const int nr = row4col_[j1];
            minVal = SPsh[j1];                     // exact double
            const int kown = j1 - tid * 4;
            if (kown >= 0 && kown < 4) usedm |= (1 << kown);
            t++;
            if (nr < 0) { jsink = j1; break; }
            i = nr;
        }

        // dual update once per augmentation (reads row4col_ BEFORE augment)
        #pragma unroll
        for (int k = 0; k < 4; k++) {
            if ((usedm >> k) & 1) {
                const int j = tid * 4 + k;
                const double d = minVal - SP[k];
                v[k] -= d;
                const int rj = row4col_[j];
                if (rj >= 0) u_[rj] += d;
            }
        }
        if (tid == 0) u_[curRow] += minVal;
        __syncthreads();

        if (tid == 0) {                            // augment
            int j = jsink;
            while (true) {
                const int ii = path_[j];
                row4col_[j] = ii;
                const int tmp = col4row_[ii];
                col4row_[ii] = j;
                if (ii == curRow) break;
                j = tmp;
            }
        }
        __syncthreads();
    }

    // col4row_[t] = assigned query for target t; emit sorted by query index.
    if (tid < TN) {
        const int a = col4row_[tid];
        int r = 0;
        #pragma unroll 8
        for (int s = 0; s < TN; ++s) r += (col4row_[s] < a);
        outRow[b * TN + r] = (float)a;
        outCol[b * TN + r] = (float)tid;
    }
}

// ---------------------------------------------------------------------------
extern "C" void kernel_launch(void* const* d_in, const int* in_sizes, int n_in,
                              void* d_out, int out_size)
{
    const float* logits  = (const float*)d_in[0];
    const float* points  = (const float*)d_in[1];
    const int*   labels  = (const int*)  d_in[2];
    const float* tpoints = (const float*)d_in[3];

    float* out    = (float*)d_out;
    float* outC   = out;
    float* outRow = out + (size_t)BS * QN * TN;
    float* outCol = outRow + BS * TN;

    cost_kernel<<<BS * QN / 8, 256>>>(logits, points, labels, tpoints, outC);
    dim3 tg(QN / 32, TN / 32, BS);
    transpose_kernel<<<tg, 1024>>>(outC);
    lsa_kernel<<<BS, 256>>>(outRow, outCol);
}

// round 8
// speedup vs baseline: 7.7941x; 1.1504x over previous
#include <cuda_runtime.h>
#include <cuda_bf16.h>
#include <cstdint>
#include <cfloat>

#define BS   16
#define QN   1024
#define CN   92
#define TN   128

// Transposed cost Ct[b][t][q] so the JV row scan is coalesced.
__device__ float g_Ct[BS * TN * QN];
// Per-(b,t) INVERTED packed row-min key (atomicMax of ~(fkey<<11|q)).
// Statically zero-initialized; atomicMax is idempotent across graph replays.
__device__ unsigned long long g_rowkeyInv[BS * TN];   // zero-init

// order-preserving fp32 -> u32 key and inverse
__device__ __forceinline__ unsigned int fkey(float x) {
    unsigned int u = __float_as_uint(x);
    return (u & 0x80000000u) ? ~u : (u ^ 0x80000000u);
}
__device__ __forceinline__ float fkey_inv(unsigned int k) {
    unsigned int u = (k & 0x80000000u) ? (k ^ 0x80000000u) : ~k;
    return __uint_as_float(u);
}
__device__ __forceinline__ unsigned long long dkey(double x) {
    unsigned long long u = __double_as_longlong(x);
    return (u & 0x8000000000000000ULL) ? ~u : (u ^ 0x8000000000000000ULL);
}

// ---------------------------------------------------------------------------
// Fused cost + transpose + row-min kernel.
// Block = 1024 threads = 32 warps; warp w computes query q0+w of batch b.
// Costs staged in a padded smem tile, then written transposed to g_Ct;
// row-min folded into the transposed pass (REDUX + one atomicMax per row seg).
// ---------------------------------------------------------------------------
__global__ void __launch_bounds__(1024)
cost_kernel(const float* __restrict__ logits,
            const float* __restrict__ points,
            const int*   __restrict__ lab32,
            const float* __restrict__ tpoints,
            float* __restrict__ outC)
{
    const int warp = threadIdx.x >> 5, lane = threadIdx.x & 31;
    const int b  = blockIdx.x >> 5;
    const int q0 = (blockIdx.x & 31) << 5;
    const int q  = q0 + warp;
    const int bq = (b << 10) + q;

    __shared__ float tile[TN][33];     // [t][q_local]
    __shared__ float sprob[32][96];
    __shared__ int   slbl[TN];
    __shared__ float stx[TN], sty[TN];
    __shared__ int   s_lbl64;

    if (threadIdx.x == 0) s_lbl64 = 1;
    __syncthreads();
    if (threadIdx.x < TN) {
        if (lab32[2 * threadIdx.x + 1] != 0) s_lbl64 = 0;
    }
    __syncthreads();
    const int lbl64 = s_lbl64;

    if (threadIdx.x < TN) {
        const int lidx = b * TN + threadIdx.x;
        slbl[threadIdx.x] = lbl64 ? lab32[2 * lidx] : lab32[lidx];
        stx[threadIdx.x]  = tpoints[lidx * 2];
        sty[threadIdx.x]  = tpoints[lidx * 2 + 1];
    }

    const float* lg = logits + (size_t)bq * CN;
    const float a  = lg[lane];
    const float bb = lg[lane + 32];
    const float c  = (lane < 28) ? lg[lane + 64] : -FLT_MAX;

    float mx = fmaxf(a, fmaxf(bb, c));
    #pragma unroll
    for (int o = 16; o > 0; o >>= 1) mx = fmaxf(mx, __shfl_xor_sync(0xffffffffu, mx, o));

    const float ea = expf(a - mx);
    const float eb = expf(bb - mx);
    const float ec = (lane < 28) ? expf(c - mx) : 0.f;
    float e = ea + eb + ec;
    #pragma unroll
    for (int o = 16; o > 0; o >>= 1) e += __shfl_xor_sync(0xffffffffu, e, o);
    const float inv = 1.f / e;

    sprob[warp][lane]      = ea * inv;
    sprob[warp][lane + 32] = eb * inv;
    if (lane < 28) sprob[warp][lane + 64] = ec * inv;

    const float px = __ldg(points + bq * 2);
    const float py = __ldg(points + bq * 2 + 1);
    __syncthreads();   // publish slbl/stx/sty (written by warps 0-3) to ALL warps

    #pragma unroll
    for (int c2 = 0; c2 < 4; c2++) {
        const int t = c2 * 32 + lane;
        const float cost = fabsf(px - stx[t]) + fabsf(py - sty[t])
                         - sprob[warp][slbl[t]];
        outC[(size_t)bq * TN + t] = cost;     // coalesced Cb write
        tile[t][warp] = cost;                 // stage for transposed write
    }
    __syncthreads();

    // Transposed write + row-min: warp handles rows t = warp, warp+32, ...
    #pragma unroll
    for (int p = 0; p < 4; p++) {
        const int t = p * 32 + warp;
        const float val = tile[t][lane];
        g_Ct[((size_t)b * TN + t) * QN + q0 + lane] = val;

        const unsigned int fk = fkey(val);
        const unsigned int mh = __reduce_min_sync(0xffffffffu, fk);
        const unsigned int win = __ffs(__ballot_sync(0xffffffffu, fk == mh)) - 1;
        if (lane == win) {
            const unsigned long long key =
                ((unsigned long long)mh << 11) | (unsigned long long)(q0 + lane);
            atomicMax(&g_rowkeyInv[b * TN + t], ~key);
        }
    }
}

// ---------------------------------------------------------------------------
// JV: row-reduction duals from g_rowkeyInv, greedy CAS assignment, then
// Dijkstra shortest augmenting paths for the ~8 unassigned rows.
// ---------------------------------------------------------------------------
__global__ void __launch_bounds__(256, 1)
lsa_kernel(float* __restrict__ outRow, float* __restrict__ outCol)
{
    const int b = blockIdx.x, tid = threadIdx.x;
    const int lane = tid & 31;

    __shared__ double u_[TN];
    __shared__ double SPsh[QN];
    __shared__ int    path_[QN];
    __shared__ int    row4col_[QN];
    __shared__ int    col4row_[TN];
    __shared__ unsigned long long s_key[3];

    const float* C = g_Ct + (size_t)b * TN * QN;
    const double DINF = 1e300;

    #pragma unroll
    for (int k = 0; k < 4; k++) row4col_[tid * 4 + k] = -1;
    if (tid == 0) { s_key[0] = ~0ULL; s_key[1] = ~0ULL; s_key[2] = ~0ULL; }
    __syncthreads();

    // ---- duals + greedy assignment from precomputed row-min keys ----
    if (tid < TN) {
        const unsigned long long key = ~g_rowkeyInv[b * TN + tid];
        const int js = (int)(key & 2047ULL);
        u_[tid] = (double)fkey_inv((unsigned int)(key >> 11));
        const int old = atomicCAS(&row4col_[js], -1, tid);
        col4row_[tid] = (old == -1) ? js : -1;
    }
    __syncthreads();

    // ---- Dijkstra augmentation for unassigned rows ----
    double v[4] = {0, 0, 0, 0};
    int t = 0;

    for (int curRow = 0; curRow < TN; ++curRow) {
        if (col4row_[curRow] >= 0) continue;

        double SP[4] = {DINF, DINF, DINF, DINF};
        int usedm = 0;
        int i = curRow;
        double minVal = 0.0;
        int jsink;

        while (true) {
            const float4 cc = __ldg((const float4*)(C + (size_t)i * QN) + tid);
            if (tid == 0) s_key[(t + 1) % 3] = ~0ULL;
            const double h = minVal - u_[i];
            const float cf[4] = {cc.x, cc.y, cc.z, cc.w};

            unsigned long long lkey = ~0ULL;
            #pragma unroll
            for (int k = 0; k < 4; k++) {
                if (!((usedm >> k) & 1)) {
                    const int j = tid * 4 + k;
                    const double r = (double)cf[k] + h - v[k];
                    if (r < SP[k]) { SP[k] = r; path_[j] = i; SPsh[j] = r; }
                    const unsigned long long kk =
                        (dkey(SP[k]) & ~2047ULL) | (unsigned long long)j;
                    if (kk < lkey) lkey = kk;
                }
            }
            // warp argmin via two hardware REDUX passes (hi word, then lo word)
            {
                const unsigned int hi = (unsigned int)(lkey >> 32);
                const unsigned int mh = __reduce_min_sync(0xffffffffu, hi);
                const unsigned int lo = (hi == mh) ? (unsigned int)lkey : 0xffffffffu;
                const unsigned int ml = __reduce_min_sync(0xffffffffu, lo);
                if (lane == 0)
                    atomicMin(&s_key[t % 3],
                              ((unsigned long long)mh << 32) | (unsigned long long)ml);
            }
            __syncthreads();                       // the ONLY per-step barrier

            const int j1 = (int)(s_key[t % 3] & 2047ULL);
            const int nr = row4col_[j1];
            minVal = SPsh[j1];                     // exact double
            const int kown = j1 - tid * 4;
            if (kown >= 0 && kown < 4) usedm |= (1 << kown);
            t++;
            if (nr < 0) { jsink = j1; break; }
            i = nr;
        }

        // dual update once per augmentation (reads row4col_ BEFORE augment)
        #pragma unroll
        for (int k = 0; k < 4; k++) {
            if ((usedm >> k) & 1) {
                const int j = tid * 4 + k;
                const double d = minVal - SP[k];
                v[k] -= d;
                const int rj = row4col_[j];
                if (rj >= 0) u_[rj] += d;
            }
        }
        if (tid == 0) u_[curRow] += minVal;
        __syncthreads();

        if (tid == 0) {                            // augment
            int j = jsink;
            while (true) {
                const int ii = path_[j];
                row4col_[j] = ii;
                const int tmp = col4row_[ii];
                col4row_[ii] = j;
                if (ii == curRow) break;
                j = tmp;
            }
        }
        __syncthreads();
    }

    // col4row_[t] = assigned query for target t; emit sorted by query index.
    if (tid < TN) {
        const int a = col4row_[tid];
        int r = 0;
        #pragma unroll 8
        for (int s = 0; s < TN; ++s) r += (col4row_[s] < a);
        outRow[b * TN + r] = (float)a;
        outCol[b * TN + r] = (float)tid;
    }
}

// ---------------------------------------------------------------------------
extern "C" void kernel_launch(void* const* d_in, const int* in_sizes, int n_in,
                              void* d_out, int out_size)
{
    const float* logits  = (const float*)d_in[0];
    const float* points  = (const float*)d_in[1];
    const int*   labels  = (const int*)  d_in[2];
    const float* tpoints = (const float*)d_in[3];

    float* out    = (float*)d_out;
    float* outC   = out;
    float* outRow = out + (size_t)BS * QN * TN;
    float* outCol = outRow + BS * TN;

    cost_kernel<<<BS * 32, 1024>>>(logits, points, labels, tpoints, outC);
    lsa_kernel<<<BS, 256>>>(outRow, outCol);
}

// round 9
// speedup vs baseline: 12.3371x; 1.5829x over previous
#include <cuda_runtime.h>
#include <cuda_bf16.h>
#include <cstdint>
#include <cfloat>

#define BS   16
#define QN   1024
#define CN   92
#define TN   128

#define SCALE_D 36028797018963968.0   // 2^55
#define LL_INF  0x3FFFFFFFFFFFFFFFLL

// Transposed int64 fixed-point cost CtI[b][t][q] (exact monotone image of fp32).
__device__ long long g_CtI[BS * TN * QN];
// Per-(b,t) INVERTED packed row-min key (atomicMax of ~(fkey<<11|q)).
// Statically zero-initialized; atomicMax is idempotent across graph replays.
__device__ unsigned long long g_rowkeyInv[BS * TN];   // zero-init

// order-preserving fp32 -> u32 key and inverse
__device__ __forceinline__ unsigned int fkey(float x) {
    unsigned int u = __float_as_uint(x);
    return (u & 0x80000000u) ? ~u : (u ^ 0x80000000u);
}
__device__ __forceinline__ float fkey_inv(unsigned int k) {
    unsigned int u = (k & 0x80000000u) ? (k ^ 0x80000000u) : ~k;
    return __uint_as_float(u);
}
// fp32 -> exact int64 fixed point (monotone; (double)val*2^55 is exact)
__device__ __forceinline__ long long cvtll(float val) {
    return (long long)((double)val * SCALE_D);
}

// ---------------------------------------------------------------------------
// Fused cost + transpose(int64) + row-min kernel. 32 warps = 32 queries/block.
// ---------------------------------------------------------------------------
__global__ void __launch_bounds__(1024)
cost_kernel(const float* __restrict__ logits,
            const float* __restrict__ points,
            const int*   __restrict__ lab32,
            const float* __restrict__ tpoints,
            float* __restrict__ outC)
{
    const int warp = threadIdx.x >> 5, lane = threadIdx.x & 31;
    const int b  = blockIdx.x >> 5;
    const int q0 = (blockIdx.x & 31) << 5;
    const int q  = q0 + warp;
    const int bq = (b << 10) + q;

    __shared__ float tile[TN][33];     // [t][q_local]
    __shared__ float sprob[32][96];
    __shared__ int   slbl[TN];
    __shared__ float stx[TN], sty[TN];
    __shared__ int   s_lbl64;

    if (threadIdx.x == 0) s_lbl64 = 1;
    __syncthreads();
    if (threadIdx.x < TN) {
        if (lab32[2 * threadIdx.x + 1] != 0) s_lbl64 = 0;
    }
    __syncthreads();
    const int lbl64 = s_lbl64;

    if (threadIdx.x < TN) {
        const int lidx = b * TN + threadIdx.x;
        slbl[threadIdx.x] = lbl64 ? lab32[2 * lidx] : lab32[lidx];
        stx[threadIdx.x]  = tpoints[lidx * 2];
        sty[threadIdx.x]  = tpoints[lidx * 2 + 1];
    }

    const float* lg = logits + (size_t)bq * CN;
    const float a  = lg[lane];
    const float bb = lg[lane + 32];
    const float c  = (lane < 28) ? lg[lane + 64] : -FLT_MAX;

    float mx = fmaxf(a, fmaxf(bb, c));
    #pragma unroll
    for (int o = 16; o > 0; o >>= 1) mx = fmaxf(mx, __shfl_xor_sync(0xffffffffu, mx, o));

    const float ea = expf(a - mx);
    const float eb = expf(bb - mx);
    const float ec = (lane < 28) ? expf(c - mx) : 0.f;
    float e = ea + eb + ec;
    #pragma unroll
    for (int o = 16; o > 0; o >>= 1) e += __shfl_xor_sync(0xffffffffu, e, o);
    const float inv = 1.f / e;

    sprob[warp][lane]      = ea * inv;
    sprob[warp][lane + 32] = eb * inv;
    if (lane < 28) sprob[warp][lane + 64] = ec * inv;

    const float px = __ldg(points + bq * 2);
    const float py = __ldg(points + bq * 2 + 1);
    __syncthreads();   // publish slbl/stx/sty to ALL warps

    #pragma unroll
    for (int c2 = 0; c2 < 4; c2++) {
        const int t = c2 * 32 + lane;
        const float cost = fabsf(px - stx[t]) + fabsf(py - sty[t])
                         - sprob[warp][slbl[t]];
        outC[(size_t)bq * TN + t] = cost;     // coalesced Cb write
        tile[t][warp] = cost;                 // stage for transposed write
    }
    __syncthreads();

    // Transposed int64 write + row-min: warp handles rows t = warp, warp+32,...
    #pragma unroll
    for (int p = 0; p < 4; p++) {
        const int t = p * 32 + warp;
        const float val = tile[t][lane];
        g_CtI[((size_t)b * TN + t) * QN + q0 + lane] = cvtll(val);

        const unsigned int fk = fkey(val);
        const unsigned int mh = __reduce_min_sync(0xffffffffu, fk);
        const unsigned int win = __ffs(__ballot_sync(0xffffffffu, fk == mh)) - 1;
        if (lane == win) {
            const unsigned long long key =
                ((unsigned long long)mh << 11) | (unsigned long long)(q0 + lane);
            atomicMax(&g_rowkeyInv[b * TN + t], ~key);
        }
    }
}

// ---------------------------------------------------------------------------
// Exact int64 JV: row-reduction duals, greedy CAS assignment, Dijkstra
// augmentation for contested rows. 1024 threads, ONE column per thread.
// All arithmetic is exact integer -> zero rounding concerns.
// ---------------------------------------------------------------------------
__global__ void __launch_bounds__(1024, 1)
lsa_kernel(float* __restrict__ outRow, float* __restrict__ outCol)
{
    const int b = blockIdx.x, tid = threadIdx.x;
    const int lane = tid & 31, warp = tid >> 5;

    __shared__ long long u_[TN];
    __shared__ long long SPsh[QN];
    __shared__ int    path_[QN];
    __shared__ int    row4col_[QN];
    __shared__ int    col4row_[TN];
    __shared__ int    list_[TN];
    __shared__ int    cnt_[4];
    __shared__ int    s_nfree;
    __shared__ unsigned long long s_key[3];

    const long long* C = g_CtI + (size_t)b * TN * QN;

    row4col_[tid] = -1;
    if (tid == 0) { s_key[0] = ~0ULL; s_key[1] = ~0ULL; s_key[2] = ~0ULL; }
    __syncthreads();

    // ---- duals + greedy assignment from precomputed row-min keys ----
    if (tid < TN) {
        const unsigned long long key = ~g_rowkeyInv[b * TN + tid];
        const int js = (int)(key & 2047ULL);
        u_[tid] = cvtll(fkey_inv((unsigned int)(key >> 11)));
        const int old = atomicCAS(&row4col_[js], -1, tid);
        col4row_[tid] = (old == -1) ? js : -1;
    }
    __syncthreads();

    // ---- build list of unassigned (contested) rows ----
    unsigned int bal = 0;
    if (tid < TN) {
        bal = __ballot_sync(0xffffffffu, col4row_[tid] < 0);
        if (lane == 0) cnt_[warp] = __popc(bal);
    }
    __syncthreads();
    if (tid < TN && col4row_[tid] < 0) {
        int base = 0;
        #pragma unroll
        for (int w = 0; w < 4; w++) if (w < warp) base += cnt_[w];
        list_[base + __popc(bal & ((1u << lane) - 1u))] = tid;
    }
    if (tid == 0) s_nfree = cnt_[0] + cnt_[1] + cnt_[2] + cnt_[3];
    __syncthreads();
    const int nfree = s_nfree;

    // ---- Dijkstra augmentation (exact int64) ----
    long long v = 0;                       // this thread's column dual
    int t = 0;

    for (int li = 0; li < nfree; ++li) {
        const int curRow = list_[li];

        long long SP = LL_INF;
        unsigned long long lkey = ~0ULL;   // cached packed key for this column
        bool used = false;
        int i = curRow;
        long long minVal = 0;
        int jsink;

        while (true) {
            const long long c = __ldg(C + (size_t)i * QN + tid);
            if (tid == 0) s_key[(t + 1) % 3] = ~0ULL;
            const long long hk = minVal - u_[i] - v;

            if (!used) {
                const long long r = c + hk;
                if (r < SP) {
                    SP = r; path_[tid] = i; SPsh[tid] = r;
                    lkey = (((unsigned long long)r ^ 0x8000000000000000ULL)
                            & ~2047ULL) | (unsigned long long)tid;
                }
            }
            // two-pass hardware REDUX argmin on the cached key
            {
                const unsigned int hi = (unsigned int)(lkey >> 32);
                const unsigned int mh = __reduce_min_sync(0xffffffffu, hi);
                const unsigned int lo = (hi == mh) ? (unsigned int)lkey : 0xffffffffu;
                const unsigned int ml = __reduce_min_sync(0xffffffffu, lo);
                if (lane == 0)
                    atomicMin(&s_key[t % 3],
                              ((unsigned long long)mh << 32) | (unsigned long long)ml);
            }
            __syncthreads();                       // the ONLY per-step barrier

            const int j1 = (int)(s_key[t % 3] & 2047ULL);
            const int nr = row4col_[j1];
            minVal = SPsh[j1];                     // exact int64
            if (tid == j1) { used = true; lkey = ~0ULL; }
            t++;
            if (nr < 0) { jsink = j1; break; }
            i = nr;
        }

        // dual update once per augmentation (reads row4col_ BEFORE augment)
        if (used) {
            const long long d = minVal - SP;
            v -= d;
            const int rj = row4col_[tid];
            if (rj >= 0) u_[rj] += d;              // assigned rows distinct
        }
        if (tid == 0) u_[curRow] += minVal;
        __syncthreads();

        if (tid == 0) {                            // augment
            int j = jsink;
            while (true) {
                const int ii = path_[j];
                row4col_[j] = ii;
                const int tmp = col4row_[ii];
                col4row_[ii] = j;
                if (ii == curRow) break;
                j = tmp;
            }
        }
        __syncthreads();
    }

    // col4row_[t] = assigned query for target t; emit sorted by query index.
    if (tid < TN) {
        const int a = col4row_[tid];
        int r = 0;
        #pragma unroll 8
        for (int s = 0; s < TN; ++s) r += (col4row_[s] < a);
        outRow[b * TN + r] = (float)a;
        outCol[b * TN + r] = (float)tid;
    }
}

// ---------------------------------------------------------------------------
extern "C" void kernel_launch(void* const* d_in, const int* in_sizes, int n_in,
                              void* d_out, int out_size)
{
    const float* logits  = (const float*)d_in[0];
    const float* points  = (const float*)d_in[1];
    const int*   labels  = (const int*)  d_in[2];
    const float* tpoints = (const float*)d_in[3];

    float* out    = (float*)d_out;
    float* outC   = out;
    float* outRow = out + (size_t)BS * QN * TN;
    float* outCol = outRow + BS * TN;

    cost_kernel<<<BS * 32, 1024>>>(logits, points, labels, tpoints, outC);
    lsa_kernel<<<BS, 1024>>>(outRow, outCol);
}